// round 11
// baseline (speedup 1.0000x reference)
#include <cuda_runtime.h>

#define N_ITEMS 20000
#define ALPHA 0.2f
#define GRID 608
#define NGROUP (GRID * 2)      // 1216 independent row pipelines
#define S64 (NGROUP * 64)

#define BARG() asm volatile("bar.sync %0, 128;" :: "r"(barid) : "memory")

__global__ __launch_bounds__(256, 4) void gat_kernel(
    const float* __restrict__ item,
    const float* __restrict__ ent,
    const int*   __restrict__ adj,
    const float* __restrict__ W,
    const float* __restrict__ a,
    float*       __restrict__ out)
{
    __shared__ float wa1s[64], wa2s[64];
    __shared__ float part[2][2][256];   // [group][parity]
    __shared__ float smsum[2][2][4];    // [group][parity][warp]
    __shared__ float s1buf[2][2];       // [group][parity]

    const int t    = threadIdx.x;
    const int gi   = t >> 7;
    const int gt   = t & 127;
    const int lane = t & 31;
    const int wg   = gt >> 5;
    const int mB   = gt >> 4;           // 0..7 : 2*wg + (lane>>4)
    const int fs   = lane & 15;
    const int fe   = gt - 64;           // epilogue f (wg>=2)
    const int barid = 1 + gi;
    const int mrow = mB + 8 * (lane & 7);  // row whose d/x this lane holds post-butterfly

    // --- wa1 = W@a1, wa2 = W@a2 (once per CTA) ---
    {
        const int f = t >> 2, q = t & 3;
        const float* wr = W + f * 64 + q * 16;
        float p1 = 0.f, p2 = 0.f;
#pragma unroll
        for (int i = 0; i < 4; ++i) {
            float4 wv = *(const float4*)(wr + i * 4);
            float4 y1 = *(const float4*)(a + q * 16 + i * 4);
            float4 y2 = *(const float4*)(a + 64 + q * 16 + i * 4);
            p1 += wv.x*y1.x + wv.y*y1.y + wv.z*y1.z + wv.w*y1.w;
            p2 += wv.x*y2.x + wv.y*y2.y + wv.z*y2.z + wv.w*y2.w;
        }
        p1 += __shfl_xor_sync(~0u, p1, 1); p1 += __shfl_xor_sync(~0u, p1, 2);
        p2 += __shfl_xor_sync(~0u, p2, 1); p2 += __shfl_xor_sync(~0u, p2, 2);
        if (q == 0) { wa1s[f] = p1; wa2s[f] = p2; }
    }
    __syncthreads();
    const float4 w2   = *(const float4*)&wa2s[fs * 4];
    const float  wa1a = wa1s[lane];
    const float  wa1b = wa1s[32 + lane];

    int n   = blockIdx.x * 2 + gi;
    int off = n * 64;

    // --- Prime row n ---
    int j0 = adj[off + lane], j1 = adj[off + 32 + lane];
    unsigned bm0 = __ballot_sync(~0u, j0 > 0);
    unsigned bm1 = __ballot_sync(~0u, j1 > 0);
    float4 v[8];
    {
        const float* eb = ent + (size_t)off * 64;
#pragma unroll
        for (int c = 0; c < 8; ++c) {
            const int m = mB + 8 * c;
            const bool lv = (m < 32) ? ((bm0 >> m) & 1u) : ((bm1 >> (m - 32)) & 1u);
            v[c] = lv ? *(const float4*)(eb + (size_t)(gt + 128 * c) * 4)
                      : make_float4(0.f, 0.f, 0.f, 0.f);
        }
    }
    bool hasN = (n + NGROUP) < N_ITEMS;
    float itA = 0.f, itB = 0.f, ieCur = 0.f, iePrev = 0.f;
    if (wg == 0) {
        itA = item[off + lane]; itB = item[off + 32 + lane];
        float p = itA * wa1a + itB * wa1b;
        p += __shfl_xor_sync(~0u, p, 16);
        p += __shfl_xor_sync(~0u, p, 8);
        p += __shfl_xor_sync(~0u, p, 4);
        p += __shfl_xor_sync(~0u, p, 2);
        p += __shfl_xor_sync(~0u, p, 1);
        if (lane == 0) s1buf[gi][0] = p;
        if (hasN) { itA = item[off + S64 + lane]; itB = item[off + S64 + 32 + lane]; }
    }
    if (wg >= 2) ieCur = item[off + fe];
    int jn0 = 0, jn1 = 0;
    if (hasN) { jn0 = adj[off + S64 + lane]; jn1 = adj[off + S64 + 32 + lane]; }
    int par = 0, offPrev = -1;
    BARG();   // s1buf[par=0] visible

    while (true) {
        // ---- d-phase (intra-warp only): 32 FMA + 8-shfl butterfly ----
        float dd[8];
#pragma unroll
        for (int c = 0; c < 8; ++c)
            dd[c] = v[c].x*w2.x + v[c].y*w2.y + v[c].z*w2.z + v[c].w*w2.w;
        float e0 = ((lane&1)? dd[1]:dd[0]) + __shfl_xor_sync(~0u, (lane&1)? dd[0]:dd[1], 1);
        float e1 = ((lane&1)? dd[3]:dd[2]) + __shfl_xor_sync(~0u, (lane&1)? dd[2]:dd[3], 1);
        float e2 = ((lane&1)? dd[5]:dd[4]) + __shfl_xor_sync(~0u, (lane&1)? dd[4]:dd[5], 1);
        float e3 = ((lane&1)? dd[7]:dd[6]) + __shfl_xor_sync(~0u, (lane&1)? dd[6]:dd[7], 1);
        float f0 = ((lane&2)? e1:e0) + __shfl_xor_sync(~0u, (lane&2)? e0:e1, 2);
        float f1 = ((lane&2)? e3:e2) + __shfl_xor_sync(~0u, (lane&2)? e2:e3, 2);
        float g0 = ((lane&4)? f1:f0) + __shfl_xor_sync(~0u, (lane&4)? f0:f1, 4);
        g0 += __shfl_xor_sync(~0u, g0, 8);

        // ---- x = exp(leaky(s1+d)) locally; warp-local Sum(x) ----
        float e = s1buf[gi][par] + g0;
        e = fmaxf(e, ALPHA * e);
        const unsigned mbit = (mrow < 32) ? ((bm0 >> mrow) & 1u) : ((bm1 >> (mrow - 32)) & 1u);
        const float x = mbit ? __expf(e) : 0.f;
        float xs = (lane & 8) ? 0.f : x;    // dedupe (lane j and j+8 hold same row)
        xs += __shfl_xor_sync(~0u, xs, 16);
        xs += __shfl_xor_sync(~0u, xs, 8);
        xs += __shfl_xor_sync(~0u, xs, 4);
        xs += __shfl_xor_sync(~0u, xs, 2);
        xs += __shfl_xor_sync(~0u, xs, 1);
        if (lane == 0) smsum[gi][par][wg] = xs;

        // ---- prev-row epilogue (wg 2-3) ----
        if (wg >= 2) {
            if (offPrev >= 0) {
                const int pp = par ^ 1;
                const float r = (part[gi][pp][fe]       + part[gi][pp][64 + fe])
                              + (part[gi][pp][128 + fe] + part[gi][pp][192 + fe]);
                const float inv = 1.0f / ((smsum[gi][pp][0] + smsum[gi][pp][1])
                                        + (smsum[gi][pp][2] + smsum[gi][pp][3]));
                out[offPrev + fe] = r * inv + iePrev;
            }
            iePrev = ieCur;
            if (hasN) ieCur = item[off + S64 + fe];
        }

        // ---- s1 for NEXT row (wg 0), one row ahead ----
        if (wg == 0 && hasN) {
            float p = itA * wa1a + itB * wa1b;
            p += __shfl_xor_sync(~0u, p, 16);
            p += __shfl_xor_sync(~0u, p, 8);
            p += __shfl_xor_sync(~0u, p, 4);
            p += __shfl_xor_sync(~0u, p, 2);
            p += __shfl_xor_sync(~0u, p, 1);
            if (lane == 0) s1buf[gi][par ^ 1] = p;
            if ((n + 2 * NGROUP) < N_ITEMS) {
                itA = item[off + 2 * S64 + lane];
                itB = item[off + 2 * S64 + 32 + lane];
            }
        }

        // ---- next-row masks + adj for row n+2 ----
        const unsigned nb0 = __ballot_sync(~0u, hasN && jn0 > 0);
        const unsigned nb1 = __ballot_sync(~0u, hasN && jn1 > 0);
        const bool hasNN = (n + 2 * NGROUP) < N_ITEMS;
        if (hasNN) { jn0 = adj[off + 2*S64 + lane]; jn1 = adj[off + 2*S64 + 32 + lane]; }

        // ---- acc (x via intra-warp shfl) interleaved with next-row LDGs ----
        {
            const float* ebN = ent + (size_t)(off + S64) * 64;
            float4 acc = make_float4(0.f, 0.f, 0.f, 0.f);
#pragma unroll
            for (int c = 0; c < 8; ++c) {
                const float xc = __shfl_sync(~0u, x, (lane & 16) | c);
                acc.x = fmaf(xc, v[c].x, acc.x);
                acc.y = fmaf(xc, v[c].y, acc.y);
                acc.z = fmaf(xc, v[c].z, acc.z);
                acc.w = fmaf(xc, v[c].w, acc.w);
                const int m = mB + 8 * c;
                const bool lv = (m < 32) ? ((nb0 >> m) & 1u) : ((nb1 >> (m - 32)) & 1u);
                v[c] = lv ? *(const float4*)(ebN + (size_t)(gt + 128 * c) * 4)
                          : make_float4(0.f, 0.f, 0.f, 0.f);
            }
            acc.x += __shfl_xor_sync(~0u, acc.x, 16);
            acc.y += __shfl_xor_sync(~0u, acc.y, 16);
            acc.z += __shfl_xor_sync(~0u, acc.z, 16);
            acc.w += __shfl_xor_sync(~0u, acc.w, 16);
            if (lane < 16) *(float4*)&part[gi][par][wg * 64 + fs * 4] = acc;
        }

        bm0 = nb0; bm1 = nb1;
        offPrev = off; off += S64; n += NGROUP; par ^= 1; hasN = hasNN;
        BARG();   // part/smsum/s1buf of this row visible; rotate
        if (n >= N_ITEMS) break;
    }

    // ---- drain: epilogue for the final row ----
    if (wg >= 2) {
        const int pp = par ^ 1;
        const float r = (part[gi][pp][fe]       + part[gi][pp][64 + fe])
                      + (part[gi][pp][128 + fe] + part[gi][pp][192 + fe]);
        const float inv = 1.0f / ((smsum[gi][pp][0] + smsum[gi][pp][1])
                                + (smsum[gi][pp][2] + smsum[gi][pp][3]));
        out[offPrev + fe] = r * inv + iePrev;
    }
}

extern "C" void kernel_launch(void* const* d_in, const int* in_sizes, int n_in,
                              void* d_out, int out_size) {
    const float* item = (const float*)d_in[0];
    const float* ent  = (const float*)d_in[1];
    const int*   adj  = (const int*)d_in[2];
    const float* W    = (const float*)d_in[3];
    const float* a    = (const float*)d_in[4];
    float* out = (float*)d_out;

    gat_kernel<<<GRID, 256>>>(item, ent, adj, W, a, out);
}